// round 2
// baseline (speedup 1.0000x reference)
#include <cuda_runtime.h>
#include <cuda_bf16.h>
#include <cstddef>

// Problem dims (fixed for this problem instance)
#define B_   2
#define NP_  512
#define NC_  512
#define D_   128
#define P_   128

#define PITCH 132            // 128 + 4 floats; 528B rows keep 16B alignment
#define SMEM_BYTES ((2 * D_ * PITCH + D_) * (int)sizeof(float))

// Scratch for layernormed p and c (device globals: allocation-free)
__device__ float g_pn[(size_t)B_ * NP_ * D_];
__device__ float g_cn[(size_t)B_ * NC_ * D_];

// ---------------------------------------------------------------------------
// LayerNorm: one warp per row, D=128 -> float4 per lane + warp shuffles.
// Handles both p (rows 0..1023) and c (rows 1024..2047) in one launch.
// ---------------------------------------------------------------------------
__global__ void ln_kernel(const float* __restrict__ p_in,
                          const float* __restrict__ c_in,
                          const float* __restrict__ pw, const float* __restrict__ pb,
                          const float* __restrict__ cw, const float* __restrict__ cb) {
    int gwarp = (blockIdx.x * blockDim.x + threadIdx.x) >> 5;
    int lane  = threadIdx.x & 31;
    if (gwarp >= B_ * (NP_ + NC_)) return;

    const float *src, *w, *bb;
    float* dst;
    int row;
    if (gwarp < B_ * NP_) { src = p_in; w = pw; bb = pb; dst = g_pn; row = gwarp; }
    else                  { src = c_in; w = cw; bb = cb; dst = g_cn; row = gwarp - B_ * NP_; }

    float4 v = reinterpret_cast<const float4*>(src + (size_t)row * D_)[lane];

    float s = v.x + v.y + v.z + v.w;
    #pragma unroll
    for (int o = 16; o > 0; o >>= 1) s += __shfl_xor_sync(0xFFFFFFFFu, s, o);
    float mu = s * (1.0f / D_);

    float dx = v.x - mu, dy = v.y - mu, dz = v.z - mu, dw = v.w - mu;
    float q = dx * dx + dy * dy + dz * dz + dw * dw;
    #pragma unroll
    for (int o = 16; o > 0; o >>= 1) q += __shfl_xor_sync(0xFFFFFFFFu, q, o);
    float inv = rsqrtf(q * (1.0f / D_) + 1e-5f);

    float4 wv = reinterpret_cast<const float4*>(w)[lane];
    float4 bv = reinterpret_cast<const float4*>(bb)[lane];
    float4 o4;
    o4.x = dx * inv * wv.x + bv.x;
    o4.y = dy * inv * wv.y + bv.y;
    o4.z = dz * inv * wv.z + bv.z;
    o4.w = dw * inv * wv.w + bv.w;
    reinterpret_cast<float4*>(dst + (size_t)row * D_)[lane] = o4;
}

// ---------------------------------------------------------------------------
// Main GEMM kernel. Grid: (jt=4, i=512, b=2). Block: 256 threads.
// Computes out[b, i, j0:j0+128, 0:128] = c_tile @ (W * p_i)^T + bias, masked.
// smem: c_s[k][j] (k-major, transposed) and wp_s[k][h] = W[h][k]*p[i][k].
// Each thread: 8x8 register tile (tx->h, ty->j).
// Masks are int32 (1/0).
// ---------------------------------------------------------------------------
__global__ __launch_bounds__(256, 1)
void gemm_kernel(const int* __restrict__ p_mask,
                 const int* __restrict__ c_mask,
                 const float* __restrict__ W,
                 const float* __restrict__ bias,
                 float* __restrict__ out) {
    extern __shared__ float sm[];
    float* c_s  = sm;                      // [D_][PITCH]  c_s[k*PITCH + j]
    float* wp_s = sm + D_ * PITCH;         // [D_][PITCH]  wp_s[k*PITCH + h]
    float* p_s  = sm + 2 * D_ * PITCH;     // [D_]

    const int jt = blockIdx.x;             // 0..3
    const int i  = blockIdx.y;             // 0..511
    const int b  = blockIdx.z;             // 0..1
    const int t  = threadIdx.x;            // 0..255
    const int j0 = jt * 128;

    // --- Phase 1: load p row (warp 0) and c tile (all threads, transposed) ---
    if (t < 32) {
        float4 v = reinterpret_cast<const float4*>(g_pn + ((size_t)b * NP_ + i) * D_)[t];
        p_s[t * 4 + 0] = v.x;
        p_s[t * 4 + 1] = v.y;
        p_s[t * 4 + 2] = v.z;
        p_s[t * 4 + 3] = v.w;
    }
    {
        const int row  = t >> 1;           // j within tile, 0..127
        const int half = t & 1;
        const float4* crow = reinterpret_cast<const float4*>(
            g_cn + ((size_t)b * NC_ + j0 + row) * D_);
        #pragma unroll
        for (int s = 0; s < 16; s++) {
            int ct = half * 16 + s;        // float4 column 0..31
            float4 v = crow[ct];
            int k = ct * 4;
            c_s[(k + 0) * PITCH + row] = v.x;
            c_s[(k + 1) * PITCH + row] = v.y;
            c_s[(k + 2) * PITCH + row] = v.z;
            c_s[(k + 3) * PITCH + row] = v.w;
        }
    }
    __syncthreads();

    // --- Phase 2: load W, scale by p, store transposed ---
    {
        const int row  = t >> 1;           // h, 0..127
        const int half = t & 1;
        const float4* wrow = reinterpret_cast<const float4*>(W + (size_t)row * D_);
        #pragma unroll
        for (int s = 0; s < 16; s++) {
            int ct = half * 16 + s;
            float4 v = wrow[ct];
            int k = ct * 4;
            wp_s[(k + 0) * PITCH + row] = v.x * p_s[k + 0];
            wp_s[(k + 1) * PITCH + row] = v.y * p_s[k + 1];
            wp_s[(k + 2) * PITCH + row] = v.z * p_s[k + 2];
            wp_s[(k + 3) * PITCH + row] = v.w * p_s[k + 3];
        }
    }
    __syncthreads();

    // --- Phase 3: 8x8 register-tile GEMM over K=128 ---
    const int tx = t & 15;                 // h dim
    const int ty = t >> 4;                 // j dim
    const int h0 = tx * 8;
    const int jr0 = ty * 8;

    float acc[8][8];
    #pragma unroll
    for (int r = 0; r < 8; r++)
        #pragma unroll
        for (int c = 0; c < 8; c++) acc[r][c] = 0.0f;

    #pragma unroll 4
    for (int k = 0; k < D_; k++) {
        const float* ck = c_s + k * PITCH + jr0;
        const float* wk = wp_s + k * PITCH + h0;
        float4 a0 = *reinterpret_cast<const float4*>(ck);
        float4 a1 = *reinterpret_cast<const float4*>(ck + 4);
        float4 b0 = *reinterpret_cast<const float4*>(wk);
        float4 b1 = *reinterpret_cast<const float4*>(wk + 4);
        float aj[8] = {a0.x, a0.y, a0.z, a0.w, a1.x, a1.y, a1.z, a1.w};
        float bh[8] = {b0.x, b0.y, b0.z, b0.w, b1.x, b1.y, b1.z, b1.w};
        #pragma unroll
        for (int r = 0; r < 8; r++)
            #pragma unroll
            for (int c = 0; c < 8; c++)
                acc[r][c] += aj[r] * bh[c];
    }

    // --- Epilogue: bias + mask, write out ---
    float4 bb0 = reinterpret_cast<const float4*>(bias + h0)[0];
    float4 bb1 = reinterpret_cast<const float4*>(bias + h0)[1];
    float bh[8] = {bb0.x, bb0.y, bb0.z, bb0.w, bb1.x, bb1.y, bb1.z, bb1.w};
    const bool pm = p_mask[b * NP_ + i] != 0;

    #pragma unroll
    for (int r = 0; r < 8; r++) {
        int j = j0 + jr0 + r;
        float scale = (pm && (c_mask[b * NC_ + j] != 0)) ? 1.0f : 0.0f;
        size_t base = ((((size_t)b * NP_ + i) * NC_ + j) * P_) + h0;
        float4 o0, o1;
        o0.x = (acc[r][0] + bh[0]) * scale;
        o0.y = (acc[r][1] + bh[1]) * scale;
        o0.z = (acc[r][2] + bh[2]) * scale;
        o0.w = (acc[r][3] + bh[3]) * scale;
        o1.x = (acc[r][4] + bh[4]) * scale;
        o1.y = (acc[r][5] + bh[5]) * scale;
        o1.z = (acc[r][6] + bh[6]) * scale;
        o1.w = (acc[r][7] + bh[7]) * scale;
        reinterpret_cast<float4*>(out + base)[0] = o0;
        reinterpret_cast<float4*>(out + base)[1] = o1;
    }
}

// ---------------------------------------------------------------------------
// inter_mask output (second output of the reference tuple). Variants for the
// possible packings of a bool output appended after the float output.
// ---------------------------------------------------------------------------
__global__ void mask_float_kernel(const int* __restrict__ p_mask,
                                  const int* __restrict__ c_mask,
                                  float* __restrict__ out, long n) {
    long idx = (long)blockIdx.x * blockDim.x + threadIdx.x;
    if (idx >= n) return;
    int j  = (int)(idx & (NC_ - 1));
    long bi = idx >> 9;
    int i  = (int)(bi & (NP_ - 1));
    int b  = (int)(bi >> 9);
    out[idx] = (p_mask[b * NP_ + i] && c_mask[b * NC_ + j]) ? 1.0f : 0.0f;
}

__global__ void mask_byte_kernel(const int* __restrict__ p_mask,
                                 const int* __restrict__ c_mask,
                                 unsigned char* __restrict__ out, long n) {
    long idx = (long)blockIdx.x * blockDim.x + threadIdx.x;
    if (idx >= n) return;
    int j  = (int)(idx & (NC_ - 1));
    long bi = idx >> 9;
    int i  = (int)(bi & (NP_ - 1));
    int b  = (int)(bi >> 9);
    out[idx] = (p_mask[b * NP_ + i] && c_mask[b * NC_ + j]) ? 1 : 0;
}

// ---------------------------------------------------------------------------
extern "C" void kernel_launch(void* const* d_in, const int* in_sizes, int n_in,
                              void* d_out, int out_size) {
    const float* p_embed = (const float*)d_in[0];
    const float* c_embed = (const float*)d_in[1];
    const int*   p_mask  = (const int*)d_in[2];
    const int*   c_mask  = (const int*)d_in[3];
    const float* ln_p_w  = (const float*)d_in[4];
    const float* ln_p_b  = (const float*)d_in[5];
    const float* ln_c_w  = (const float*)d_in[6];
    const float* ln_c_b  = (const float*)d_in[7];
    const float* W_out   = (const float*)d_in[8];
    const float* b_out   = (const float*)d_in[9];
    float* out = (float*)d_out;

    cudaFuncSetAttribute(gemm_kernel,
                         cudaFuncAttributeMaxDynamicSharedMemorySize, SMEM_BYTES);

    // LayerNorm p and c (2048 rows, 1 warp each, 8 warps per block)
    ln_kernel<<<(B_ * (NP_ + NC_)) / 8, 256>>>(p_embed, c_embed,
                                               ln_p_w, ln_p_b, ln_c_w, ln_c_b);

    // Main fused interaction GEMM
    dim3 grid(NC_ / 128, NP_, B_);
    gemm_kernel<<<grid, 256, SMEM_BYTES>>>(p_mask, c_mask, W_out, b_out, out);

    // Second output: inter_mask, packed after inter. Handle either a
    // float/int32-sized tail (one element per mask entry) or a raw
    // bool-byte tail, based on out_size.
    const long inter_elems = (long)B_ * NP_ * NC_ * P_;        // 67108864
    const long mask_elems  = (long)B_ * NP_ * NC_;             // 524288
    long extra = (long)out_size - inter_elems;
    if (extra == mask_elems / 4) {
        // bool bytes appended, measured in float-sized elements
        mask_byte_kernel<<<(int)((mask_elems + 255) / 256), 256>>>(
            p_mask, c_mask, (unsigned char*)(out + inter_elems), mask_elems);
    } else if (extra > 0) {
        // mask stored as the output dtype (float32-sized), one per entry
        long n = extra < mask_elems ? extra : mask_elems;
        mask_float_kernel<<<(int)((n + 255) / 256), 256>>>(
            p_mask, c_mask, out + inter_elems, n);
    }
}

// round 4
// speedup vs baseline: 2.0433x; 2.0433x over previous
#include <cuda_runtime.h>
#include <cuda_bf16.h>
#include <cstdint>
#include <cstddef>

// Problem dims (fixed)
#define B_   2
#define NP_  512
#define NC_  512
#define D_   128
#define P_   128

// ---------------- device scratch (allocation-free) ----------------
__device__ __align__(16) float         g_pn [(size_t)B_ * NP_ * D_];
__device__ __align__(16) __nv_bfloat16 g_chi[(size_t)B_ * NC_ * D_];
__device__ __align__(16) __nv_bfloat16 g_clo[(size_t)B_ * NC_ * D_];

__device__ __forceinline__ uint32_t smem_u32(const void* p) {
    uint32_t a;
    asm("{ .reg .u64 t; cvta.to.shared.u64 t, %1; cvt.u32.u64 %0, t; }"
        : "=r"(a) : "l"(p));
    return a;
}

// ---------------- SMEM layout ----------------
#define LDA      272                       // 128 bf16 = 256B + 16B pad (conflict-free ldmatrix)
#define SM_P     0
#define SM_BIAS  512
#define SM_SCALE 1024
#define SM_AHI   2048
#define SM_ALO   (SM_AHI + 128 * LDA)
#define SM_BHI   (SM_ALO + 128 * LDA)
#define SM_BLO   (SM_BHI + 128 * LDA)
#define SM_TOTAL (SM_BLO + 128 * LDA)      // 141312 bytes

// ---------------------------------------------------------------------------
// LayerNorm: one warp per row. p rows -> fp32; c rows -> split bf16 hi/lo.
// ---------------------------------------------------------------------------
__global__ void ln_kernel(const float* __restrict__ p_in,
                          const float* __restrict__ c_in,
                          const float* __restrict__ pw, const float* __restrict__ pb,
                          const float* __restrict__ cw, const float* __restrict__ cb) {
    int gwarp = (blockIdx.x * blockDim.x + threadIdx.x) >> 5;
    int lane  = threadIdx.x & 31;
    if (gwarp >= B_ * (NP_ + NC_)) return;

    bool is_p = gwarp < B_ * NP_;
    int row = is_p ? gwarp : gwarp - B_ * NP_;
    const float* src = is_p ? p_in : c_in;
    const float* w   = is_p ? pw : cw;
    const float* bb  = is_p ? pb : cb;

    float4 v = reinterpret_cast<const float4*>(src + (size_t)row * D_)[lane];

    float s = v.x + v.y + v.z + v.w;
    #pragma unroll
    for (int o = 16; o > 0; o >>= 1) s += __shfl_xor_sync(0xFFFFFFFFu, s, o);
    float mu = s * (1.0f / D_);

    float dx = v.x - mu, dy = v.y - mu, dz = v.z - mu, dw = v.w - mu;
    float q = dx * dx + dy * dy + dz * dz + dw * dw;
    #pragma unroll
    for (int o = 16; o > 0; o >>= 1) q += __shfl_xor_sync(0xFFFFFFFFu, q, o);
    float inv = rsqrtf(q * (1.0f / D_) + 1e-5f);

    float4 wv = reinterpret_cast<const float4*>(w)[lane];
    float4 bv = reinterpret_cast<const float4*>(bb)[lane];
    float o0 = dx * inv * wv.x + bv.x;
    float o1 = dy * inv * wv.y + bv.y;
    float o2 = dz * inv * wv.z + bv.z;
    float o3 = dw * inv * wv.w + bv.w;

    if (is_p) {
        float4 o4 = {o0, o1, o2, o3};
        reinterpret_cast<float4*>(g_pn + (size_t)row * D_)[lane] = o4;
    } else {
        __nv_bfloat16 h0 = __float2bfloat16(o0), h1 = __float2bfloat16(o1);
        __nv_bfloat16 h2 = __float2bfloat16(o2), h3 = __float2bfloat16(o3);
        __nv_bfloat16 l0 = __float2bfloat16(o0 - __bfloat162float(h0));
        __nv_bfloat16 l1 = __float2bfloat16(o1 - __bfloat162float(h1));
        __nv_bfloat16 l2 = __float2bfloat16(o2 - __bfloat162float(h2));
        __nv_bfloat16 l3 = __float2bfloat16(o3 - __bfloat162float(h3));
        uint2 hw, lw;
        hw.x = (uint32_t)__bfloat16_as_ushort(h0) | ((uint32_t)__bfloat16_as_ushort(h1) << 16);
        hw.y = (uint32_t)__bfloat16_as_ushort(h2) | ((uint32_t)__bfloat16_as_ushort(h3) << 16);
        lw.x = (uint32_t)__bfloat16_as_ushort(l0) | ((uint32_t)__bfloat16_as_ushort(l1) << 16);
        lw.y = (uint32_t)__bfloat16_as_ushort(l2) | ((uint32_t)__bfloat16_as_ushort(l3) << 16);
        reinterpret_cast<uint2*>(g_chi + (size_t)row * D_)[lane] = hw;
        reinterpret_cast<uint2*>(g_clo + (size_t)row * D_)[lane] = lw;
    }
}

// ---------------------------------------------------------------------------
// Split-bf16 warp-MMA interaction kernel.
// Grid (jt=4, i=512, b=2), 256 threads = 8 warps in 2(m) x 4(n).
// CTA computes out[b, i, j0:j0+128, :] via 3-pass split bf16:
//   c*wp ~= chi*wphi + clo*wphi + chi*wplo
// ---------------------------------------------------------------------------
__global__ __launch_bounds__(256, 1)
void gemm_mma_kernel(const int* __restrict__ p_mask,
                     const int* __restrict__ c_mask,
                     const float* __restrict__ W,
                     const float* __restrict__ bias,
                     float* __restrict__ out) {
    extern __shared__ char smem[];
    const uint32_t sb = smem_u32(smem);
    float* p_s     = reinterpret_cast<float*>(smem + SM_P);
    float* bias_s  = reinterpret_cast<float*>(smem + SM_BIAS);
    float* scale_s = reinterpret_cast<float*>(smem + SM_SCALE);

    const int jt = blockIdx.x;
    const int i  = blockIdx.y;
    const int b  = blockIdx.z;
    const int t  = threadIdx.x;
    const int wid  = t >> 5;
    const int lane = t & 31;
    const int j0 = jt * 128;

    // --- small loads: p row, bias, mask scales ---
    if (t < 32) {
        float4 v = reinterpret_cast<const float4*>(g_pn + ((size_t)b * NP_ + i) * D_)[t];
        p_s[t * 4 + 0] = v.x; p_s[t * 4 + 1] = v.y;
        p_s[t * 4 + 2] = v.z; p_s[t * 4 + 3] = v.w;
    } else if (t < 64) {
        reinterpret_cast<float4*>(bias_s)[t - 32] =
            reinterpret_cast<const float4*>(bias)[t - 32];
    } else if (t < 192) {
        int jl = t - 64;
        scale_s[jl] = (p_mask[b * NP_ + i] != 0 && c_mask[b * NC_ + j0 + jl] != 0)
                      ? 1.0f : 0.0f;
    }

    // --- A tiles (c hi/lo) via cp.async: 2 matrices x 128 rows x 16 chunks ---
    #pragma unroll 4
    for (int idx = t; idx < 4096; idx += 256) {
        int mat = idx >> 11;
        int rem = idx & 2047;
        int row = rem >> 4;
        int c16 = rem & 15;
        uint32_t dst = sb + (mat ? SM_ALO : SM_AHI) + row * LDA + c16 * 16;
        const __nv_bfloat16* src =
            (mat ? g_clo : g_chi) + ((size_t)b * NC_ + j0 + row) * D_ + c16 * 8;
        asm volatile("cp.async.cg.shared.global [%0], [%1], 16;"
                     :: "r"(dst), "l"(src) : "memory");
    }
    __syncthreads();   // p_s ready for W scaling

    // --- Build B = W o p_i, split hi/lo bf16, padded rows ---
    #pragma unroll 4
    for (int u = t; u < 4096; u += 256) {
        int row = u >> 5;          // h
        int q   = u & 31;          // float4 index
        float4 w4 = reinterpret_cast<const float4*>(W + (size_t)row * D_)[q];
        int k = q * 4;
        float v0 = w4.x * p_s[k + 0];
        float v1 = w4.y * p_s[k + 1];
        float v2 = w4.z * p_s[k + 2];
        float v3 = w4.w * p_s[k + 3];
        __nv_bfloat16 h0 = __float2bfloat16(v0), h1 = __float2bfloat16(v1);
        __nv_bfloat16 h2 = __float2bfloat16(v2), h3 = __float2bfloat16(v3);
        __nv_bfloat16 l0 = __float2bfloat16(v0 - __bfloat162float(h0));
        __nv_bfloat16 l1 = __float2bfloat16(v1 - __bfloat162float(h1));
        __nv_bfloat16 l2 = __float2bfloat16(v2 - __bfloat162float(h2));
        __nv_bfloat16 l3 = __float2bfloat16(v3 - __bfloat162float(h3));
        uint2 hw, lw;
        hw.x = (uint32_t)__bfloat16_as_ushort(h0) | ((uint32_t)__bfloat16_as_ushort(h1) << 16);
        hw.y = (uint32_t)__bfloat16_as_ushort(h2) | ((uint32_t)__bfloat16_as_ushort(h3) << 16);
        lw.x = (uint32_t)__bfloat16_as_ushort(l0) | ((uint32_t)__bfloat16_as_ushort(l1) << 16);
        lw.y = (uint32_t)__bfloat16_as_ushort(l2) | ((uint32_t)__bfloat16_as_ushort(l3) << 16);
        *reinterpret_cast<uint2*>(smem + SM_BHI + row * LDA + k * 2) = hw;
        *reinterpret_cast<uint2*>(smem + SM_BLO + row * LDA + k * 2) = lw;
    }
    asm volatile("cp.async.wait_all;" ::: "memory");
    __syncthreads();

    // --- Mainloop ---
    const int wm = wid & 1;      // 0..1  (m: 64 rows each)
    const int wn = wid >> 1;     // 0..3  (n: 32 cols each)

    float acc[4][4][4];
    #pragma unroll
    for (int mf = 0; mf < 4; mf++)
        #pragma unroll
        for (int nf = 0; nf < 4; nf++)
            #pragma unroll
            for (int r = 0; r < 4; r++) acc[mf][nf][r] = 0.0f;

    const uint32_t a_lane = (uint32_t)((wm * 64 + (lane & 15)) * LDA + (lane >> 4) * 16);
    const uint32_t b_lane = (uint32_t)((wn * 32 + (lane & 15)) * LDA + (lane >> 4) * 16);
    const uint32_t aoffs[3] = {SM_AHI, SM_ALO, SM_AHI};
    const uint32_t boffs[3] = {SM_BHI, SM_BHI, SM_BLO};

    #pragma unroll 1
    for (int pass = 0; pass < 3; pass++) {
        const uint32_t abase = sb + aoffs[pass] + a_lane;
        const uint32_t bbase = sb + boffs[pass] + b_lane;
        #pragma unroll
        for (int ks = 0; ks < 8; ks++) {
            uint32_t ar[4][4];
            uint32_t br[2][4];
            #pragma unroll
            for (int mf = 0; mf < 4; mf++) {
                uint32_t addr = abase + mf * (16 * LDA) + ks * 32;
                asm volatile("ldmatrix.sync.aligned.m8n8.x4.shared.b16 {%0,%1,%2,%3}, [%4];"
                             : "=r"(ar[mf][0]), "=r"(ar[mf][1]),
                               "=r"(ar[mf][2]), "=r"(ar[mf][3]) : "r"(addr));
            }
            #pragma unroll
            for (int np = 0; np < 2; np++) {
                uint32_t addr = bbase + np * (16 * LDA) + ks * 32;
                asm volatile("ldmatrix.sync.aligned.m8n8.x4.shared.b16 {%0,%1,%2,%3}, [%4];"
                             : "=r"(br[np][0]), "=r"(br[np][1]),
                               "=r"(br[np][2]), "=r"(br[np][3]) : "r"(addr));
            }
            #pragma unroll
            for (int mf = 0; mf < 4; mf++) {
                #pragma unroll
                for (int nf = 0; nf < 4; nf++) {
                    const int np = nf >> 1, sel = nf & 1;
                    asm volatile(
                        "mma.sync.aligned.m16n8k16.row.col.f32.bf16.bf16.f32 "
                        "{%0,%1,%2,%3}, {%4,%5,%6,%7}, {%8,%9}, {%0,%1,%2,%3};"
                        : "+f"(acc[mf][nf][0]), "+f"(acc[mf][nf][1]),
                          "+f"(acc[mf][nf][2]), "+f"(acc[mf][nf][3])
                        : "r"(ar[mf][0]), "r"(ar[mf][1]), "r"(ar[mf][2]), "r"(ar[mf][3]),
                          "r"(br[np][sel]), "r"(br[np][2 + sel]));
                }
            }
        }
    }

    // --- Epilogue: bias + mask, fp32 stores ---
    const int g   = lane >> 2;
    const int tig = lane & 3;
    #pragma unroll
    for (int mf = 0; mf < 4; mf++) {
        const int jl = wm * 64 + mf * 16 + g;
        const float s0 = scale_s[jl];
        const float s1 = scale_s[jl + 8];
        float* r0p = out + (((size_t)b * NP_ + i) * NC_ + j0 + jl) * P_ + wn * 32 + tig * 2;
        float* r1p = r0p + (size_t)8 * P_;
        #pragma unroll
        for (int nf = 0; nf < 4; nf++) {
            const int h = wn * 32 + nf * 8 + tig * 2;
            float2 v0, v1;
            v0.x = (acc[mf][nf][0] + bias_s[h])     * s0;
            v0.y = (acc[mf][nf][1] + bias_s[h + 1]) * s0;
            v1.x = (acc[mf][nf][2] + bias_s[h])     * s1;
            v1.y = (acc[mf][nf][3] + bias_s[h + 1]) * s1;
            *reinterpret_cast<float2*>(r0p + nf * 8) = v0;
            *reinterpret_cast<float2*>(r1p + nf * 8) = v1;
        }
    }
}

// ---------------------------------------------------------------------------
// inter_mask second-output kernels
// ---------------------------------------------------------------------------
__global__ void mask_float_kernel(const int* __restrict__ p_mask,
                                  const int* __restrict__ c_mask,
                                  float* __restrict__ out, long n) {
    long idx = (long)blockIdx.x * blockDim.x + threadIdx.x;
    if (idx >= n) return;
    int j  = (int)(idx & (NC_ - 1));
    long bi = idx >> 9;
    int i  = (int)(bi & (NP_ - 1));
    int b  = (int)(bi >> 9);
    out[idx] = (p_mask[b * NP_ + i] && c_mask[b * NC_ + j]) ? 1.0f : 0.0f;
}
__global__ void mask_byte_kernel(const int* __restrict__ p_mask,
                                 const int* __restrict__ c_mask,
                                 unsigned char* __restrict__ out, long n) {
    long idx = (long)blockIdx.x * blockDim.x + threadIdx.x;
    if (idx >= n) return;
    int j  = (int)(idx & (NC_ - 1));
    long bi = idx >> 9;
    int i  = (int)(bi & (NP_ - 1));
    int b  = (int)(bi >> 9);
    out[idx] = (p_mask[b * NP_ + i] && c_mask[b * NC_ + j]) ? 1 : 0;
}

// ---------------------------------------------------------------------------
extern "C" void kernel_launch(void* const* d_in, const int* in_sizes, int n_in,
                              void* d_out, int out_size) {
    const float* p_embed = (const float*)d_in[0];
    const float* c_embed = (const float*)d_in[1];
    const int*   p_mask  = (const int*)d_in[2];
    const int*   c_mask  = (const int*)d_in[3];
    const float* ln_p_w  = (const float*)d_in[4];
    const float* ln_p_b  = (const float*)d_in[5];
    const float* ln_c_w  = (const float*)d_in[6];
    const float* ln_c_b  = (const float*)d_in[7];
    const float* W_out   = (const float*)d_in[8];
    const float* b_out   = (const float*)d_in[9];
    float* out = (float*)d_out;

    cudaFuncSetAttribute(gemm_mma_kernel,
                         cudaFuncAttributeMaxDynamicSharedMemorySize, SM_TOTAL);

    // LayerNorm + bf16 split for c
    ln_kernel<<<(B_ * (NP_ + NC_)) / 8, 256>>>(p_embed, c_embed,
                                               ln_p_w, ln_p_b, ln_c_w, ln_c_b);

    // Split-bf16 tensor-core interaction GEMM
    dim3 grid(NC_ / 128, NP_, B_);
    gemm_mma_kernel<<<grid, 256, SM_TOTAL>>>(p_mask, c_mask, W_out, b_out, out);

    // Second output tail (inter_mask), format-adaptive
    const long inter_elems = (long)B_ * NP_ * NC_ * P_;
    const long mask_elems  = (long)B_ * NP_ * NC_;
    long extra = (long)out_size - inter_elems;
    if (extra == mask_elems / 4) {
        mask_byte_kernel<<<(int)((mask_elems + 255) / 256), 256>>>(
            p_mask, c_mask, (unsigned char*)(out + inter_elems), mask_elems);
    } else if (extra > 0) {
        long n = extra < mask_elems ? extra : mask_elems;
        mask_float_kernel<<<(int)((n + 255) / 256), 256>>>(
            p_mask, c_mask, out + inter_elems, n);
    }
}

// round 5
// speedup vs baseline: 3.8361x; 1.8774x over previous
#include <cuda_runtime.h>
#include <cuda_bf16.h>
#include <cuda_fp16.h>
#include <cstdint>
#include <cstddef>

// Problem dims (fixed)
#define B_   2
#define NP_  512
#define NC_  512
#define D_   128
#define P_   128

// ---------------- device scratch (allocation-free) ----------------
__device__ __align__(16) float  g_pn[(size_t)B_ * NP_ * D_];   // layernormed p, fp32
__device__ __align__(16) __half g_ch[(size_t)B_ * NC_ * D_];   // layernormed c, fp16

__device__ __forceinline__ uint32_t smem_u32(const void* p) {
    uint32_t a;
    asm("{ .reg .u64 t; cvta.to.shared.u64 t, %1; cvt.u32.u64 %0, t; }"
        : "=r"(a) : "l"(p));
    return a;
}

// ---------------- SMEM layout ----------------
#define LDA      272                      // 128 fp16 = 256B + 16B pad
#define SM_P     0
#define SM_BIAS  512
#define SM_SCALE 1024
#define SM_A     2048
#define SM_BHI   (SM_A   + 128 * LDA)
#define SM_BLO   (SM_BHI + 128 * LDA)
#define SM_TOTAL (SM_BLO + 128 * LDA)     // 106496 bytes -> 2 CTAs/SM

// ---------------------------------------------------------------------------
// LayerNorm: one warp per row. p rows -> fp32; c rows -> fp16.
// ---------------------------------------------------------------------------
__global__ void ln_kernel(const float* __restrict__ p_in,
                          const float* __restrict__ c_in,
                          const float* __restrict__ pw, const float* __restrict__ pb,
                          const float* __restrict__ cw, const float* __restrict__ cb) {
    int gwarp = (blockIdx.x * blockDim.x + threadIdx.x) >> 5;
    int lane  = threadIdx.x & 31;
    if (gwarp >= B_ * (NP_ + NC_)) return;

    bool is_p = gwarp < B_ * NP_;
    int row = is_p ? gwarp : gwarp - B_ * NP_;
    const float* src = is_p ? p_in : c_in;
    const float* w   = is_p ? pw : cw;
    const float* bb  = is_p ? pb : cb;

    float4 v = reinterpret_cast<const float4*>(src + (size_t)row * D_)[lane];

    float s = v.x + v.y + v.z + v.w;
    #pragma unroll
    for (int o = 16; o > 0; o >>= 1) s += __shfl_xor_sync(0xFFFFFFFFu, s, o);
    float mu = s * (1.0f / D_);

    float dx = v.x - mu, dy = v.y - mu, dz = v.z - mu, dw = v.w - mu;
    float q = dx * dx + dy * dy + dz * dz + dw * dw;
    #pragma unroll
    for (int o = 16; o > 0; o >>= 1) q += __shfl_xor_sync(0xFFFFFFFFu, q, o);
    float inv = rsqrtf(q * (1.0f / D_) + 1e-5f);

    float4 wv = reinterpret_cast<const float4*>(w)[lane];
    float4 bv = reinterpret_cast<const float4*>(bb)[lane];
    float o0 = dx * inv * wv.x + bv.x;
    float o1 = dy * inv * wv.y + bv.y;
    float o2 = dz * inv * wv.z + bv.z;
    float o3 = dw * inv * wv.w + bv.w;

    if (is_p) {
        float4 o4 = {o0, o1, o2, o3};
        reinterpret_cast<float4*>(g_pn + (size_t)row * D_)[lane] = o4;
    } else {
        __half2 h01 = __floats2half2_rn(o0, o1);
        __half2 h23 = __floats2half2_rn(o2, o3);
        uint2 hw;
        hw.x = *reinterpret_cast<uint32_t*>(&h01);
        hw.y = *reinterpret_cast<uint32_t*>(&h23);
        reinterpret_cast<uint2*>(g_ch + (size_t)row * D_)[lane] = hw;
    }
}

// ---------------------------------------------------------------------------
// Asymmetric-split fp16 warp-MMA interaction kernel.
// Grid (jt=4, i=512, b=2), 256 threads = 8 warps in 2(m) x 4(n).
// out = A(fp16) @ (Bhi + Blo)^T, A = c_ln fp16-rounded, B = W o p_i split.
// Both B terms accumulate into the same fp32 acc in one fused K loop.
// ---------------------------------------------------------------------------
__global__ __launch_bounds__(256, 2)
void gemm_mma_kernel(const int* __restrict__ p_mask,
                     const int* __restrict__ c_mask,
                     const float* __restrict__ W,
                     const float* __restrict__ bias,
                     float* __restrict__ out) {
    extern __shared__ char smem[];
    const uint32_t sb = smem_u32(smem);
    float* p_s     = reinterpret_cast<float*>(smem + SM_P);
    float* bias_s  = reinterpret_cast<float*>(smem + SM_BIAS);
    float* scale_s = reinterpret_cast<float*>(smem + SM_SCALE);

    const int jt = blockIdx.x;
    const int i  = blockIdx.y;
    const int b  = blockIdx.z;
    const int t  = threadIdx.x;
    const int wid  = t >> 5;
    const int lane = t & 31;
    const int j0 = jt * 128;

    // --- small loads: p row, bias, mask scales ---
    if (t < 32) {
        float4 v = reinterpret_cast<const float4*>(g_pn + ((size_t)b * NP_ + i) * D_)[t];
        p_s[t * 4 + 0] = v.x; p_s[t * 4 + 1] = v.y;
        p_s[t * 4 + 2] = v.z; p_s[t * 4 + 3] = v.w;
    } else if (t < 64) {
        reinterpret_cast<float4*>(bias_s)[t - 32] =
            reinterpret_cast<const float4*>(bias)[t - 32];
    } else if (t < 192) {
        int jl = t - 64;
        scale_s[jl] = (p_mask[b * NP_ + i] != 0 && c_mask[b * NC_ + j0 + jl] != 0)
                      ? 1.0f : 0.0f;
    }

    // --- A tile (c fp16) via cp.async: 128 rows x 16 chunks of 16B ---
    #pragma unroll 8
    for (int idx = t; idx < 2048; idx += 256) {
        int row = idx >> 4;
        int c16 = idx & 15;
        uint32_t dst = sb + SM_A + row * LDA + c16 * 16;
        const __half* src = g_ch + ((size_t)b * NC_ + j0 + row) * D_ + c16 * 8;
        asm volatile("cp.async.cg.shared.global [%0], [%1], 16;"
                     :: "r"(dst), "l"(src) : "memory");
    }
    __syncthreads();   // p_s ready

    // --- Build B = W o p_i, split fp16 hi/lo ---
    #pragma unroll 4
    for (int u = t; u < 4096; u += 256) {
        int row = u >> 5;          // h
        int q   = u & 31;          // float4 index
        float4 w4 = reinterpret_cast<const float4*>(W + (size_t)row * D_)[q];
        int k = q * 4;
        float v0 = w4.x * p_s[k + 0];
        float v1 = w4.y * p_s[k + 1];
        float v2 = w4.z * p_s[k + 2];
        float v3 = w4.w * p_s[k + 3];
        __half2 h01 = __floats2half2_rn(v0, v1);
        __half2 h23 = __floats2half2_rn(v2, v3);
        float2 f01 = __half22float2(h01);
        float2 f23 = __half22float2(h23);
        __half2 l01 = __floats2half2_rn(v0 - f01.x, v1 - f01.y);
        __half2 l23 = __floats2half2_rn(v2 - f23.x, v3 - f23.y);
        uint2 hw, lw;
        hw.x = *reinterpret_cast<uint32_t*>(&h01);
        hw.y = *reinterpret_cast<uint32_t*>(&h23);
        lw.x = *reinterpret_cast<uint32_t*>(&l01);
        lw.y = *reinterpret_cast<uint32_t*>(&l23);
        *reinterpret_cast<uint2*>(smem + SM_BHI + row * LDA + k * 2) = hw;
        *reinterpret_cast<uint2*>(smem + SM_BLO + row * LDA + k * 2) = lw;
    }
    asm volatile("cp.async.wait_all;" ::: "memory");
    __syncthreads();

    // --- Mainloop: fused hi+lo accumulation ---
    const int wm = wid & 1;      // m: 64 rows each
    const int wn = wid >> 1;     // n: 32 cols each

    float acc[4][4][4];
    #pragma unroll
    for (int mf = 0; mf < 4; mf++)
        #pragma unroll
        for (int nf = 0; nf < 4; nf++)
            #pragma unroll
            for (int r = 0; r < 4; r++) acc[mf][nf][r] = 0.0f;

    const uint32_t a_lane = (uint32_t)((wm * 64 + (lane & 15)) * LDA + (lane >> 4) * 16);
    const uint32_t b_lane = (uint32_t)((wn * 32 + (lane & 15)) * LDA + (lane >> 4) * 16);
    const uint32_t abase  = sb + SM_A   + a_lane;
    const uint32_t bhbase = sb + SM_BHI + b_lane;
    const uint32_t blbase = sb + SM_BLO + b_lane;

    #pragma unroll
    for (int ks = 0; ks < 8; ks++) {
        uint32_t ar[4][4];
        uint32_t bh[2][4];
        uint32_t bl[2][4];
        #pragma unroll
        for (int mf = 0; mf < 4; mf++) {
            uint32_t addr = abase + mf * (16 * LDA) + ks * 32;
            asm volatile("ldmatrix.sync.aligned.m8n8.x4.shared.b16 {%0,%1,%2,%3}, [%4];"
                         : "=r"(ar[mf][0]), "=r"(ar[mf][1]),
                           "=r"(ar[mf][2]), "=r"(ar[mf][3]) : "r"(addr));
        }
        #pragma unroll
        for (int np = 0; np < 2; np++) {
            uint32_t addr = bhbase + np * (16 * LDA) + ks * 32;
            asm volatile("ldmatrix.sync.aligned.m8n8.x4.shared.b16 {%0,%1,%2,%3}, [%4];"
                         : "=r"(bh[np][0]), "=r"(bh[np][1]),
                           "=r"(bh[np][2]), "=r"(bh[np][3]) : "r"(addr));
        }
        #pragma unroll
        for (int np = 0; np < 2; np++) {
            uint32_t addr = blbase + np * (16 * LDA) + ks * 32;
            asm volatile("ldmatrix.sync.aligned.m8n8.x4.shared.b16 {%0,%1,%2,%3}, [%4];"
                         : "=r"(bl[np][0]), "=r"(bl[np][1]),
                           "=r"(bl[np][2]), "=r"(bl[np][3]) : "r"(addr));
        }
        #pragma unroll
        for (int mf = 0; mf < 4; mf++) {
            #pragma unroll
            for (int nf = 0; nf < 4; nf++) {
                const int np = nf >> 1, sel = nf & 1;
                asm volatile(
                    "mma.sync.aligned.m16n8k16.row.col.f32.f16.f16.f32 "
                    "{%0,%1,%2,%3}, {%4,%5,%6,%7}, {%8,%9}, {%0,%1,%2,%3};"
                    : "+f"(acc[mf][nf][0]), "+f"(acc[mf][nf][1]),
                      "+f"(acc[mf][nf][2]), "+f"(acc[mf][nf][3])
                    : "r"(ar[mf][0]), "r"(ar[mf][1]), "r"(ar[mf][2]), "r"(ar[mf][3]),
                      "r"(bh[np][sel]), "r"(bh[np][2 + sel]));
                asm volatile(
                    "mma.sync.aligned.m16n8k16.row.col.f32.f16.f16.f32 "
                    "{%0,%1,%2,%3}, {%4,%5,%6,%7}, {%8,%9}, {%0,%1,%2,%3};"
                    : "+f"(acc[mf][nf][0]), "+f"(acc[mf][nf][1]),
                      "+f"(acc[mf][nf][2]), "+f"(acc[mf][nf][3])
                    : "r"(ar[mf][0]), "r"(ar[mf][1]), "r"(ar[mf][2]), "r"(ar[mf][3]),
                      "r"(bl[np][sel]), "r"(bl[np][2 + sel]));
            }
        }
    }

    // --- Epilogue: bias + mask, fp32 stores ---
    const int g   = lane >> 2;
    const int tig = lane & 3;
    #pragma unroll
    for (int mf = 0; mf < 4; mf++) {
        const int jl = wm * 64 + mf * 16 + g;
        const float s0 = scale_s[jl];
        const float s1 = scale_s[jl + 8];
        float* r0p = out + (((size_t)b * NP_ + i) * NC_ + j0 + jl) * P_ + wn * 32 + tig * 2;
        float* r1p = r0p + (size_t)8 * P_;
        #pragma unroll
        for (int nf = 0; nf < 4; nf++) {
            const int h = wn * 32 + nf * 8 + tig * 2;
            float2 v0, v1;
            v0.x = (acc[mf][nf][0] + bias_s[h])     * s0;
            v0.y = (acc[mf][nf][1] + bias_s[h + 1]) * s0;
            v1.x = (acc[mf][nf][2] + bias_s[h])     * s1;
            v1.y = (acc[mf][nf][3] + bias_s[h + 1]) * s1;
            *reinterpret_cast<float2*>(r0p + nf * 8) = v0;
            *reinterpret_cast<float2*>(r1p + nf * 8) = v1;
        }
    }
}

// ---------------------------------------------------------------------------
// inter_mask second-output kernels
// ---------------------------------------------------------------------------
__global__ void mask_float_kernel(const int* __restrict__ p_mask,
                                  const int* __restrict__ c_mask,
                                  float* __restrict__ out, long n) {
    long idx = (long)blockIdx.x * blockDim.x + threadIdx.x;
    if (idx >= n) return;
    int j  = (int)(idx & (NC_ - 1));
    long bi = idx >> 9;
    int i  = (int)(bi & (NP_ - 1));
    int b  = (int)(bi >> 9);
    out[idx] = (p_mask[b * NP_ + i] && c_mask[b * NC_ + j]) ? 1.0f : 0.0f;
}
__global__ void mask_byte_kernel(const int* __restrict__ p_mask,
                                 const int* __restrict__ c_mask,
                                 unsigned char* __restrict__ out, long n) {
    long idx = (long)blockIdx.x * blockDim.x + threadIdx.x;
    if (idx >= n) return;
    int j  = (int)(idx & (NC_ - 1));
    long bi = idx >> 9;
    int i  = (int)(bi & (NP_ - 1));
    int b  = (int)(bi >> 9);
    out[idx] = (p_mask[b * NP_ + i] && c_mask[b * NC_ + j]) ? 1 : 0;
}

// ---------------------------------------------------------------------------
extern "C" void kernel_launch(void* const* d_in, const int* in_sizes, int n_in,
                              void* d_out, int out_size) {
    const float* p_embed = (const float*)d_in[0];
    const float* c_embed = (const float*)d_in[1];
    const int*   p_mask  = (const int*)d_in[2];
    const int*   c_mask  = (const int*)d_in[3];
    const float* ln_p_w  = (const float*)d_in[4];
    const float* ln_p_b  = (const float*)d_in[5];
    const float* ln_c_w  = (const float*)d_in[6];
    const float* ln_c_b  = (const float*)d_in[7];
    const float* W_out   = (const float*)d_in[8];
    const float* b_out   = (const float*)d_in[9];
    float* out = (float*)d_out;

    cudaFuncSetAttribute(gemm_mma_kernel,
                         cudaFuncAttributeMaxDynamicSharedMemorySize, SM_TOTAL);

    // LayerNorm (p -> fp32, c -> fp16)
    ln_kernel<<<(B_ * (NP_ + NC_)) / 8, 256>>>(p_embed, c_embed,
                                               ln_p_w, ln_p_b, ln_c_w, ln_c_b);

    // Asymmetric-split fp16 tensor-core interaction GEMM
    dim3 grid(NC_ / 128, NP_, B_);
    gemm_mma_kernel<<<grid, 256, SM_TOTAL>>>(p_mask, c_mask, W_out, b_out, out);

    // Second output tail (inter_mask), format-adaptive
    const long inter_elems = (long)B_ * NP_ * NC_ * P_;
    const long mask_elems  = (long)B_ * NP_ * NC_;
    long extra = (long)out_size - inter_elems;
    if (extra == mask_elems / 4) {
        mask_byte_kernel<<<(int)((mask_elems + 255) / 256), 256>>>(
            p_mask, c_mask, (unsigned char*)(out + inter_elems), mask_elems);
    } else if (extra > 0) {
        long n = extra < mask_elems ? extra : mask_elems;
        mask_float_kernel<<<(int)((n + 255) / 256), 256>>>(
            p_mask, c_mask, out + inter_elems, n);
    }
}